// round 12
// baseline (speedup 1.0000x reference)
#include <cuda_runtime.h>
#include <cuda_fp16.h>
#include <cstdint>

#define D_DIM 1024
#define K_TOP 307
#define MAX_N 65536

// ============================ PTX helpers ===================================
__device__ __forceinline__ uint32_t smem_u32(const void* p) {
    uint32_t a;
    asm("{ .reg .u64 t; cvta.to.shared.u64 t, %1; cvt.u32.u64 %0, t; }" : "=r"(a) : "l"(p));
    return a;
}
#define CPA16(saddr, gptr) \
    asm volatile("cp.async.cg.shared.global [%0], [%1], 16;" :: "r"(saddr), "l"(gptr) : "memory")
#define CP_COMMIT() asm volatile("cp.async.commit_group;" ::: "memory")
#define CP_WAIT1()  asm volatile("cp.async.wait_group 1;" ::: "memory")
#define CP_WAIT0()  asm volatile("cp.async.wait_group 0;" ::: "memory")

#define LDSM_X4(r0, r1, r2, r3, addr) \
    asm volatile("ldmatrix.sync.aligned.m8n8.x4.shared.b16 {%0,%1,%2,%3}, [%4];" \
        : "=r"(r0), "=r"(r1), "=r"(r2), "=r"(r3) : "r"(addr))

#define MMA16816F16(d, a, b0, b1) \
    asm volatile("mma.sync.aligned.m16n8k16.row.col.f32.f16.f16.f32 " \
        "{%0,%1,%2,%3}, {%4,%5,%6,%7}, {%8,%9}, {%0,%1,%2,%3};" \
        : "+f"((d)[0]), "+f"((d)[1]), "+f"((d)[2]), "+f"((d)[3]) \
        : "r"((a)[0]), "r"((a)[1]), "r"((a)[2]), "r"((a)[3]), "r"(b0), "r"(b1))

// ============================ numeric helpers ================================
__device__ __forceinline__ float sigmoid_acc(float z) {
    float x = -z;
    x = fminf(fmaxf(x, -87.0f), 87.0f);
    float t = x * 1.4426950408889634f;
    float n = rintf(t);
    float r = fmaf(n, -0.693145751953125f, x);
    r = fmaf(n, -1.42860676533018687e-06f, r);
    float p = 1.9875691500e-4f;
    p = fmaf(p, r, 1.3981999507e-3f);
    p = fmaf(p, r, 8.3333331174e-3f);
    p = fmaf(p, r, 4.1665795894e-2f);
    p = fmaf(p, r, 1.6666665459e-1f);
    p = fmaf(p, r, 5.0000001201e-1f);
    float y = fmaf(r * r, p, r) + 1.0f;
    int   i  = (int)n;
    float sc = __int_as_float((i + 127) << 23);
    return 1.0f / (1.0f + y * sc);
}

// fp16 2-way split: x = h + m * 2^-11  (m stored pre-scaled by 2048, normal range)
__device__ __forceinline__ void split2h(float x, uint16_t& h, uint16_t& m) {
    __half hh = __float2half_rn(x);
    float  hf = __half2float(hh);
    __half mh = __float2half_rn((x - hf) * 2048.0f);
    h = __half_as_ushort(hh);
    m = __half_as_ushort(mh);
}

// ============================ pre-split storage ==============================
__device__ __align__(16) uint16_t g_Wh[D_DIM * D_DIM];
__device__ __align__(16) uint16_t g_Wm[D_DIM * D_DIM];
__device__ __align__(16) uint16_t g_Xh[(size_t)MAX_N * D_DIM];
__device__ __align__(16) uint16_t g_Xm[(size_t)MAX_N * D_DIM];
__device__ unsigned int g_tile_ctr;

__global__ __launch_bounds__(256)
void split2_kernel(const float* __restrict__ src, uint16_t* __restrict__ oh,
                   uint16_t* __restrict__ om) {
    if (blockIdx.x == 0 && threadIdx.x == 0) g_tile_ctr = 0;  // reset for gemm
    size_t gid = (size_t)blockIdx.x * 256 + threadIdx.x;  // one 8-float group
    float4 a = ((const float4*)src)[2 * gid];
    float4 c = ((const float4*)src)[2 * gid + 1];
    float v[8] = {a.x, a.y, a.z, a.w, c.x, c.y, c.z, c.w};
    uint16_t h[8], m[8];
#pragma unroll
    for (int i = 0; i < 8; i++) split2h(v[i], h[i], m[i]);
    uint4 H = {(uint32_t)h[0] | ((uint32_t)h[1] << 16), (uint32_t)h[2] | ((uint32_t)h[3] << 16),
               (uint32_t)h[4] | ((uint32_t)h[5] << 16), (uint32_t)h[6] | ((uint32_t)h[7] << 16)};
    uint4 M = {(uint32_t)m[0] | ((uint32_t)m[1] << 16), (uint32_t)m[2] | ((uint32_t)m[3] << 16),
               (uint32_t)m[4] | ((uint32_t)m[5] << 16), (uint32_t)m[6] | ((uint32_t)m[7] << 16)};
    ((uint4*)oh)[gid] = H;
    ((uint4*)om)[gid] = M;
}

// ============================ GEMM (persistent HMMA) =========================
// CTA tile 64(M) x 128(N). Persistent CTAs pull tiles from a global counter.
// cp.async double-buffer streams chunks continuously across tile boundaries.
// 3 fp16 products: hH -> per-chunk ah (RN-folded into tot); hM'+m'H -> al.
#define ATILE   8192                    // 64 x 64 fp16
#define BTILE   16384                   // 128 x 64 fp16
#define BOFF    (2 * ATILE)             // 16384
#define STAGE_B (2 * ATILE + 2 * BTILE) // 49152
#define SMEM_GEMM (2 * STAGE_B)         // 98304
#define NCHUNK  (D_DIM / 64)            // 16

__device__ __forceinline__ void issue_stage(uint32_t sb, int stage, int brow,
                                            int bcol, int k0, int tid) {
    const uint32_t st = sb + stage * STAGE_B;
#pragma unroll
    for (int j = 0; j < 2; j++) {
        int g = tid + j * 256;
        int row = g >> 3, cc = g & 7;
        uint32_t sw = (uint32_t)(row * 128 + ((cc ^ (row & 7)) << 4));
        size_t ga = (size_t)(brow + row) * D_DIM + k0 + cc * 8;
        CPA16(st + 0 * ATILE + sw, g_Xh + ga);
        CPA16(st + 1 * ATILE + sw, g_Xm + ga);
    }
#pragma unroll
    for (int j = 0; j < 4; j++) {
        int g = tid + j * 256;
        int row = g >> 3, cc = g & 7;
        uint32_t sw = (uint32_t)(row * 128 + ((cc ^ (row & 7)) << 4));
        size_t gb = (size_t)(bcol + row) * D_DIM + k0 + cc * 8;
        CPA16(st + BOFF + 0 * BTILE + sw, g_Wh + gb);
        CPA16(st + BOFF + 1 * BTILE + sw, g_Wm + gb);
    }
    CP_COMMIT();
}

__global__ __launch_bounds__(256, 1)
void gemm_hmma_kernel(const float* __restrict__ bias, float* __restrict__ S,
                      int NT) {
    extern __shared__ char smem[];
    __shared__ int s_t[3];
    const uint32_t sb = smem_u32(smem);
    const int tid  = threadIdx.x;
    const int lane = tid & 31;
    const int wid  = tid >> 5;
    const int mg   = wid >> 2;          // 0..1 : rows mg*32..+32
    const int ng   = wid & 3;           // 0..3 : cols ng*32..+32

    if (tid == 0) {
        s_t[0] = (int)atomicAdd(&g_tile_ctr, 1u);
        s_t[1] = (int)atomicAdd(&g_tile_ctr, 1u);
    }
    __syncthreads();
    int cur = s_t[0], nxt = s_t[1];
    if (cur >= NT) return;

    // ---- ldmatrix lane addressing (validated rounds 8-11) ----
    const int aRow = mg * 32 + (((lane >> 3) & 1) << 3) + (lane & 7);   // <64
    const int aC   = (lane >> 4);
    const uint32_t aRB = (uint32_t)(aRow * 128);
    const int aXor = aRow & 7;
    const int bRow = ng * 32 + (((lane >> 4) & 1) << 3) + (lane & 7);   // <128
    const int bC   = (lane >> 3) & 1;
    const uint32_t bRB = (uint32_t)(bRow * 128);
    const int bXor = bRow & 7;

    float tot[2][4][4];   // fp32 total of hH chunks (RN folds)
    float ah[2][4][4];    // per-chunk hH accumulator
    float al[2][4][4];    // persistent scaled-residual accumulator
#pragma unroll
    for (int mt = 0; mt < 2; mt++)
#pragma unroll
        for (int nt = 0; nt < 4; nt++)
#pragma unroll
            for (int e = 0; e < 4; e++) { tot[mt][nt][e] = 0.0f; al[mt][nt][e] = 0.0f; }

    int g = 0;  // global chunk-stream counter (parity = buffer index)
    issue_stage(sb, 0, (cur >> 3) << 6, (cur & 7) << 7, 0, tid);

    const float RS = 1.0f / 2048.0f;
    while (true) {
        const int brow = (cur >> 3) << 6;
        const int bcol = (cur & 7) << 7;

        for (int c = 0; c < NCHUNK; ++c) {
            // issue next stream chunk (cross-tile continuous)
            bool issued;
            if (c < NCHUNK - 1) {
                issue_stage(sb, (g + 1) & 1, brow, bcol, (c + 1) * 64, tid);
                issued = true;
            } else if (nxt < NT) {
                issue_stage(sb, (g + 1) & 1, (nxt >> 3) << 6, (nxt & 7) << 7, 0, tid);
                issued = true;
            } else {
                issued = false;
            }
            if (issued) CP_WAIT1(); else CP_WAIT0();
            __syncthreads();
            if (c == 1 && tid == 0) s_t[2] = (int)atomicAdd(&g_tile_ctr, 1u);

            const uint32_t stA = sb + (g & 1) * STAGE_B;
            const uint32_t stB = stA + BOFF;

            // zero the per-chunk hH accumulator
#pragma unroll
            for (int mt = 0; mt < 2; mt++)
#pragma unroll
                for (int nt = 0; nt < 4; nt++)
#pragma unroll
                    for (int e = 0; e < 4; e++) ah[mt][nt][e] = 0.0f;

#pragma unroll
            for (int ks = 0; ks < 4; ++ks) {
                uint32_t a[2][2][4];
                uint32_t b[2][2][4];
#pragma unroll
                for (int s = 0; s < 2; s++) {
#pragma unroll
                    for (int mt = 0; mt < 2; mt++) {
                        uint32_t addr = stA + s * ATILE + aRB + mt * 2048 +
                                        (uint32_t)(((aC + 2 * ks) ^ aXor) << 4);
                        LDSM_X4(a[s][mt][0], a[s][mt][1], a[s][mt][2], a[s][mt][3], addr);
                    }
#pragma unroll
                    for (int np = 0; np < 2; np++) {
                        uint32_t addr = stB + s * BTILE + bRB + np * 2048 +
                                        (uint32_t)(((bC + 2 * ks) ^ bXor) << 4);
                        LDSM_X4(b[s][np][0], b[s][np][1], b[s][np][2], b[s][np][3], addr);
                    }
                }
                // p0: h*H -> ah
#pragma unroll
                for (int mt = 0; mt < 2; mt++)
#pragma unroll
                    for (int np = 0; np < 2; np++) {
                        MMA16816F16(ah[mt][2 * np + 0], a[0][mt], b[0][np][0], b[0][np][1]);
                        MMA16816F16(ah[mt][2 * np + 1], a[0][mt], b[0][np][2], b[0][np][3]);
                    }
                // p1: h*M' -> al
#pragma unroll
                for (int mt = 0; mt < 2; mt++)
#pragma unroll
                    for (int np = 0; np < 2; np++) {
                        MMA16816F16(al[mt][2 * np + 0], a[0][mt], b[1][np][0], b[1][np][1]);
                        MMA16816F16(al[mt][2 * np + 1], a[0][mt], b[1][np][2], b[1][np][3]);
                    }
                // p2: m'*H -> al
#pragma unroll
                for (int mt = 0; mt < 2; mt++)
#pragma unroll
                    for (int np = 0; np < 2; np++) {
                        MMA16816F16(al[mt][2 * np + 0], a[1][mt], b[0][np][0], b[0][np][1]);
                        MMA16816F16(al[mt][2 * np + 1], a[1][mt], b[0][np][2], b[0][np][3]);
                    }
            }
            // RN fold of the chunk's hH partial into the fp32 total
#pragma unroll
            for (int mt = 0; mt < 2; mt++)
#pragma unroll
                for (int nt = 0; nt < 4; nt++)
#pragma unroll
                    for (int e = 0; e < 4; e++) tot[mt][nt][e] += ah[mt][nt][e];
            __syncthreads();
            g++;
        }

        // ---- epilogue for tile `cur` (overlaps with in-flight next prefetch) ----
#pragma unroll
        for (int mt = 0; mt < 2; mt++) {
            const int m0 = brow + mg * 32 + mt * 16 + (lane >> 2);
#pragma unroll
            for (int nt = 0; nt < 4; nt++) {
                const int n0 = bcol + ng * 32 + nt * 8 + 2 * (lane & 3);
                const float2 bb = *(const float2*)&bias[n0];
                float2 o0, o1;
                o0.x = sigmoid_acc(fmaf(al[mt][nt][0], RS, tot[mt][nt][0]) + bb.x);
                o0.y = sigmoid_acc(fmaf(al[mt][nt][1], RS, tot[mt][nt][1]) + bb.y);
                o1.x = sigmoid_acc(fmaf(al[mt][nt][2], RS, tot[mt][nt][2]) + bb.x);
                o1.y = sigmoid_acc(fmaf(al[mt][nt][3], RS, tot[mt][nt][3]) + bb.y);
                *(float2*)&S[(size_t)m0 * D_DIM + n0]       = o0;
                *(float2*)&S[(size_t)(m0 + 8) * D_DIM + n0] = o1;
            }
        }

        cur = nxt;
        nxt = s_t[2];
        if (cur >= NT) break;
        // reset accumulators for next tile
#pragma unroll
        for (int mt = 0; mt < 2; mt++)
#pragma unroll
            for (int nt = 0; nt < 4; nt++)
#pragma unroll
                for (int e = 0; e < 4; e++) { tot[mt][nt][e] = 0.0f; al[mt][nt][e] = 0.0f; }
    }
}

// ============================ top-k mask =====================================
// 2 radix passes (16-bit prefix) + tie-class candidate ranking (round 11).
__global__ __launch_bounds__(256)
void topk_mask_kernel(const float* __restrict__ X, const float* __restrict__ S,
                      float* __restrict__ O) {
    const int row = blockIdx.x;
    const int t   = threadIdx.x;
    const int lane = t & 31, wrp = t >> 5;
    const size_t base = (size_t)row * D_DIM;

    const uint4 u = ((const uint4*)(S + base))[t];

    __shared__ int hist[256];
    __shared__ int sscan[256];
    __shared__ int wsum[8];
    __shared__ uint32_t sh_pref;
    __shared__ int sh_need;
    __shared__ int ccount;
    __shared__ uint32_t candv[64];
    __shared__ uint16_t candi[64];
    __shared__ uint32_t selbmp[32];

    uint32_t prefix = 0;
    int need = K_TOP;

#pragma unroll
    for (int p = 0; p < 2; p++) {
        const int shift = 24 - (p << 3);
        const uint32_t dm = (p == 0) ? 0u : 0xFF000000u;
        hist[t] = 0;
        __syncthreads();
        if ((u.x & dm) == prefix) atomicAdd(&hist[(u.x >> shift) & 255], 1);
        if ((u.y & dm) == prefix) atomicAdd(&hist[(u.y >> shift) & 255], 1);
        if ((u.z & dm) == prefix) atomicAdd(&hist[(u.z >> shift) & 255], 1);
        if ((u.w & dm) == prefix) atomicAdd(&hist[(u.w >> shift) & 255], 1);
        __syncthreads();
        int s = hist[t];
#pragma unroll
        for (int off = 1; off < 32; off <<= 1) {
            int v = __shfl_down_sync(0xffffffffu, s, off);
            if (lane + off < 32) s += v;
        }
        if (lane == 0) wsum[wrp] = s;
        __syncthreads();
        int add = 0;
#pragma unroll
        for (int w2 = 0; w2 < 8; w2++) add += (w2 > wrp) ? wsum[w2] : 0;
        const int ge = s + add;
        sscan[t] = ge;
        __syncthreads();
        const int nxt = (t < 255) ? sscan[t + 1] : 0;
        if (ge >= need && nxt < need) {
            sh_pref = prefix | ((uint32_t)t << shift);
            sh_need = need - nxt;
        }
        __syncthreads();
        prefix = sh_pref;
        need   = sh_need;
    }

    // ---- gather tie-class candidates (top16 == prefix bits) ----
    if (t == 0) ccount = 0;
    if (t < 32) selbmp[t] = 0;
    __syncthreads();
    const uint32_t p16 = prefix;
    const int idx0 = t << 2;
    {
        const uint32_t vv[4] = {u.x, u.y, u.z, u.w};
#pragma unroll
        for (int k = 0; k < 4; k++) {
            if ((vv[k] & 0xFFFF0000u) == p16) {
                int pos = atomicAdd(&ccount, 1);
                if (pos < 64) { candv[pos] = vv[k]; candi[pos] = (uint16_t)(idx0 + k); }
            }
        }
    }
    __syncthreads();
    const int cnt = ccount;

    const float4 xv = ((const float4*)(X + base))[t];
    float4 o;

    if (cnt <= 64) {
        if (t < cnt) {
            const uint32_t v = candv[t];
            const uint32_t idx = candi[t];
            int r = 0;
            for (int j = 0; j < cnt; j++) {
                const uint32_t vj = candv[j];
                r += (vj > v) || (vj == v && candi[j] < idx);
            }
            if (r < need) atomicOr(&selbmp[idx >> 5], 1u << (idx & 31));
        }
        __syncthreads();
        const uint32_t h0 = u.x & 0xFFFF0000u, h1 = u.y & 0xFFFF0000u;
        const uint32_t h2 = u.z & 0xFFFF0000u, h3 = u.w & 0xFFFF0000u;
        const bool s0 = (h0 > p16) || (h0 == p16 && ((selbmp[(idx0 + 0) >> 5] >> ((idx0 + 0) & 31)) & 1u));
        const bool s1 = (h1 > p16) || (h1 == p16 && ((selbmp[(idx0 + 1) >> 5] >> ((idx0 + 1) & 31)) & 1u));
        const bool s2 = (h2 > p16) || (h2 == p16 && ((selbmp[(idx0 + 2) >> 5] >> ((idx0 + 2) & 31)) & 1u));
        const bool s3 = (h3 > p16) || (h3 == p16 && ((selbmp[(idx0 + 3) >> 5] >> ((idx0 + 3) & 31)) & 1u));
        o.x = s0 ? xv.x : 0.0f;
        o.y = s1 ? xv.y : 0.0f;
        o.z = s2 ? xv.z : 0.0f;
        o.w = s3 ? xv.w : 0.0f;
    } else {
        // ---- fallback: finish radix passes 2,3 then rank ties (rare) ----
        __syncthreads();
#pragma unroll
        for (int p = 2; p < 4; p++) {
            const int shift = 24 - (p << 3);
            const uint32_t dm = (p == 2) ? 0xFFFF0000u : 0xFFFFFF00u;
            hist[t] = 0;
            __syncthreads();
            if ((u.x & dm) == prefix) atomicAdd(&hist[(u.x >> shift) & 255], 1);
            if ((u.y & dm) == prefix) atomicAdd(&hist[(u.y >> shift) & 255], 1);
            if ((u.z & dm) == prefix) atomicAdd(&hist[(u.z >> shift) & 255], 1);
            if ((u.w & dm) == prefix) atomicAdd(&hist[(u.w >> shift) & 255], 1);
            __syncthreads();
            int s = hist[t];
#pragma unroll
            for (int off = 1; off < 32; off <<= 1) {
                int v = __shfl_down_sync(0xffffffffu, s, off);
                if (lane + off < 32) s += v;
            }
            if (lane == 0) wsum[wrp] = s;
            __syncthreads();
            int add = 0;
#pragma unroll
            for (int w2 = 0; w2 < 8; w2++) add += (w2 > wrp) ? wsum[w2] : 0;
            const int ge = s + add;
            sscan[t] = ge;
            __syncthreads();
            const int nxt = (t < 255) ? sscan[t + 1] : 0;
            if (ge >= need && nxt < need) {
                sh_pref = prefix | ((uint32_t)t << shift);
                sh_need = need - nxt;
            }
            __syncthreads();
            prefix = sh_pref;
            need   = sh_need;
            __syncthreads();
        }
        const uint32_t T = prefix;
        const int e0 = (u.x == T), e1 = (u.y == T), e2 = (u.z == T), e3 = (u.w == T);
        const int cnt4 = e0 + e1 + e2 + e3;
        int incl = cnt4;
#pragma unroll
        for (int off = 1; off < 32; off <<= 1) {
            int v = __shfl_up_sync(0xffffffffu, incl, off);
            if (lane >= off) incl += v;
        }
        if (lane == 31) wsum[wrp] = incl;
        __syncthreads();
        if (t == 0) {
            int ssum = 0;
#pragma unroll
            for (int i = 0; i < 8; i++) { int v = wsum[i]; wsum[i] = ssum; ssum += v; }
        }
        __syncthreads();
        int rank = wsum[wrp] + (incl - cnt4);
        const bool s0 = (u.x > T) || (e0 && rank < need); rank += e0;
        const bool s1 = (u.y > T) || (e1 && rank < need); rank += e1;
        const bool s2 = (u.z > T) || (e2 && rank < need); rank += e2;
        const bool s3 = (u.w > T) || (e3 && rank < need);
        o.x = s0 ? xv.x : 0.0f;
        o.y = s1 ? xv.y : 0.0f;
        o.z = s2 ? xv.z : 0.0f;
        o.w = s3 ? xv.w : 0.0f;
    }
    ((float4*)(O + base))[t] = o;
}

// ============================ launch =========================================
extern "C" void kernel_launch(void* const* d_in, const int* in_sizes, int n_in,
                              void* d_out, int out_size) {
    const float* X = (const float*)d_in[0];  // [N, 1024]
    const float* W = (const float*)d_in[1];  // [1024, 1024]
    const float* b = (const float*)d_in[2];  // [1024]
    float* out = (float*)d_out;              // [2, N, 1024]

    const int N = in_sizes[0] / D_DIM;
    float* S = out + (size_t)N * D_DIM;
    const int NT = (N / 64) * (D_DIM / 128);

    uint16_t *wh, *wm, *xh, *xm;
    cudaGetSymbolAddress((void**)&wh, g_Wh);
    cudaGetSymbolAddress((void**)&wm, g_Wm);
    cudaGetSymbolAddress((void**)&xh, g_Xh);
    cudaGetSymbolAddress((void**)&xm, g_Xm);

    cudaFuncSetAttribute(gemm_hmma_kernel,
                         cudaFuncAttributeMaxDynamicSharedMemorySize, SMEM_GEMM);

    split2_kernel<<<D_DIM * D_DIM / 8 / 256, 256>>>(W, wh, wm);
    split2_kernel<<<(int)((size_t)N * D_DIM / 8 / 256), 256>>>(X, xh, xm);
    gemm_hmma_kernel<<<304, 256, SMEM_GEMM>>>(b, S, NT);
    topk_mask_kernel<<<N, 256>>>(X, S, out);
}

// round 13
// speedup vs baseline: 1.2272x; 1.2272x over previous
#include <cuda_runtime.h>
#include <cuda_fp16.h>
#include <cstdint>

#define D_DIM 1024
#define K_TOP 307
#define MAX_N 65536

// ============================ PTX helpers ===================================
__device__ __forceinline__ uint32_t smem_u32(const void* p) {
    uint32_t a;
    asm("{ .reg .u64 t; cvta.to.shared.u64 t, %1; cvt.u32.u64 %0, t; }" : "=r"(a) : "l"(p));
    return a;
}
#define CPA16(saddr, gptr) \
    asm volatile("cp.async.cg.shared.global [%0], [%1], 16;" :: "r"(saddr), "l"(gptr) : "memory")
#define CP_COMMIT() asm volatile("cp.async.commit_group;" ::: "memory")
#define CP_WAIT2()  asm volatile("cp.async.wait_group 2;" ::: "memory")
#define CP_WAIT1()  asm volatile("cp.async.wait_group 1;" ::: "memory")
#define CP_WAIT0()  asm volatile("cp.async.wait_group 0;" ::: "memory")

#define LDSM_X4(r0, r1, r2, r3, addr) \
    asm volatile("ldmatrix.sync.aligned.m8n8.x4.shared.b16 {%0,%1,%2,%3}, [%4];" \
        : "=r"(r0), "=r"(r1), "=r"(r2), "=r"(r3) : "r"(addr))

#define MMA16816F16(d, a, b0, b1) \
    asm volatile("mma.sync.aligned.m16n8k16.row.col.f32.f16.f16.f32 " \
        "{%0,%1,%2,%3}, {%4,%5,%6,%7}, {%8,%9}, {%0,%1,%2,%3};" \
        : "+f"((d)[0]), "+f"((d)[1]), "+f"((d)[2]), "+f"((d)[3]) \
        : "r"((a)[0]), "r"((a)[1]), "r"((a)[2]), "r"((a)[3]), "r"(b0), "r"(b1))

// ============================ numeric helpers ================================
__device__ __forceinline__ float sigmoid_acc(float z) {
    float x = -z;
    x = fminf(fmaxf(x, -87.0f), 87.0f);
    float t = x * 1.4426950408889634f;
    float n = rintf(t);
    float r = fmaf(n, -0.693145751953125f, x);
    r = fmaf(n, -1.42860676533018687e-06f, r);
    float p = 1.9875691500e-4f;
    p = fmaf(p, r, 1.3981999507e-3f);
    p = fmaf(p, r, 8.3333331174e-3f);
    p = fmaf(p, r, 4.1665795894e-2f);
    p = fmaf(p, r, 1.6666665459e-1f);
    p = fmaf(p, r, 5.0000001201e-1f);
    float y = fmaf(r * r, p, r) + 1.0f;
    int   i  = (int)n;
    float sc = __int_as_float((i + 127) << 23);
    return 1.0f / (1.0f + y * sc);
}

// fp16 2-way split: x = h + m * 2^-11  (m stored pre-scaled by 2048, normal range)
__device__ __forceinline__ void split2h(float x, uint16_t& h, uint16_t& m) {
    __half hh = __float2half_rn(x);
    float  hf = __half2float(hh);
    __half mh = __float2half_rn((x - hf) * 2048.0f);
    h = __half_as_ushort(hh);
    m = __half_as_ushort(mh);
}

// ============================ pre-split storage ==============================
__device__ __align__(16) uint16_t g_Wh[D_DIM * D_DIM];
__device__ __align__(16) uint16_t g_Wm[D_DIM * D_DIM];
__device__ __align__(16) uint16_t g_Xh[(size_t)MAX_N * D_DIM];
__device__ __align__(16) uint16_t g_Xm[(size_t)MAX_N * D_DIM];

__global__ __launch_bounds__(256)
void split2_kernel(const float* __restrict__ src, uint16_t* __restrict__ oh,
                   uint16_t* __restrict__ om) {
    size_t gid = (size_t)blockIdx.x * 256 + threadIdx.x;  // one 8-float group
    float4 a = ((const float4*)src)[2 * gid];
    float4 c = ((const float4*)src)[2 * gid + 1];
    float v[8] = {a.x, a.y, a.z, a.w, c.x, c.y, c.z, c.w};
    uint16_t h[8], m[8];
#pragma unroll
    for (int i = 0; i < 8; i++) split2h(v[i], h[i], m[i]);
    uint4 H = {(uint32_t)h[0] | ((uint32_t)h[1] << 16), (uint32_t)h[2] | ((uint32_t)h[3] << 16),
               (uint32_t)h[4] | ((uint32_t)h[5] << 16), (uint32_t)h[6] | ((uint32_t)h[7] << 16)};
    uint4 M = {(uint32_t)m[0] | ((uint32_t)m[1] << 16), (uint32_t)m[2] | ((uint32_t)m[3] << 16),
               (uint32_t)m[4] | ((uint32_t)m[5] << 16), (uint32_t)m[6] | ((uint32_t)m[7] << 16)};
    ((uint4*)oh)[gid] = H;
    ((uint4*)om)[gid] = M;
}

// ============================ GEMM (HMMA fp16 mma.sync) ======================
// CTA tile 64(M) x 128(N), K chunks of 64. 4-stage cp.async ring (prefetch
// depth 2, ONE barrier per chunk). Fragments double-buffered across k-steps
// (LDSM for ks+1 issued before MMAs of ks). 3 fp16 products:
//   hH -> per-chunk ah (RN-folded into tot);  hM' + m'H -> persistent al.
#define ATILE   8192                    // 64 x 64 fp16
#define BTILE   16384                   // 128 x 64 fp16
#define BOFF    (2 * ATILE)             // 16384
#define STAGE_B (2 * ATILE + 2 * BTILE) // 49152
#define NSTAGE  4
#define SMEM_GEMM (NSTAGE * STAGE_B)    // 196608
#define NCHUNK  (D_DIM / 64)            // 16

__global__ __launch_bounds__(256, 1)
void gemm_hmma_kernel(const float* __restrict__ bias, float* __restrict__ S) {
    extern __shared__ char smem[];
    const uint32_t sb = smem_u32(smem);
    const int tid  = threadIdx.x;
    const int lane = tid & 31;
    const int wid  = tid >> 5;
    const int mg   = wid >> 2;          // 0..1 : rows mg*32..+32
    const int ng   = wid & 3;           // 0..3 : cols ng*32..+32
    const int brow = blockIdx.y << 6;   // 64-row tile
    const int bcol = blockIdx.x << 7;   // 128-col tile

#define ISSUE_STAGE(c)                                                        \
    do {                                                                      \
        const int k0_ = (c) * 64;                                             \
        const uint32_t st_ = sb + ((c) & (NSTAGE - 1)) * STAGE_B;             \
        _Pragma("unroll")                                                     \
        for (int j = 0; j < 2; j++) {                                         \
            int g = tid + j * 256;                                            \
            int row = g >> 3, cc = g & 7;                                     \
            uint32_t sw = (uint32_t)(row * 128 + ((cc ^ (row & 7)) << 4));    \
            size_t ga = (size_t)(brow + row) * D_DIM + k0_ + cc * 8;          \
            CPA16(st_ + 0 * ATILE + sw, g_Xh + ga);                           \
            CPA16(st_ + 1 * ATILE + sw, g_Xm + ga);                           \
        }                                                                     \
        _Pragma("unroll")                                                     \
        for (int j = 0; j < 4; j++) {                                         \
            int g = tid + j * 256;                                            \
            int row = g >> 3, cc = g & 7;                                     \
            uint32_t sw = (uint32_t)(row * 128 + ((cc ^ (row & 7)) << 4));    \
            size_t gb = (size_t)(bcol + row) * D_DIM + k0_ + cc * 8;          \
            CPA16(st_ + BOFF + 0 * BTILE + sw, g_Wh + gb);                    \
            CPA16(st_ + BOFF + 1 * BTILE + sw, g_Wm + gb);                    \
        }                                                                     \
        CP_COMMIT();                                                          \
    } while (0)

    // ---- ldmatrix lane addressing (validated rounds 8-11) ----
    const int aRow = mg * 32 + (((lane >> 3) & 1) << 3) + (lane & 7);   // <64
    const int aC   = (lane >> 4);
    const uint32_t aRB = (uint32_t)(aRow * 128);
    const int aXor = aRow & 7;
    const int bRow = ng * 32 + (((lane >> 4) & 1) << 3) + (lane & 7);   // <128
    const int bC   = (lane >> 3) & 1;
    const uint32_t bRB = (uint32_t)(bRow * 128);
    const int bXor = bRow & 7;

// load all 8 fragments for k-step `ks` from stage bases stA_/stB_ into buffer q
#define LOAD_FRAGS(q, ks, stA_, stB_)                                          \
    do {                                                                       \
        _Pragma("unroll")                                                      \
        for (int s = 0; s < 2; s++) {                                          \
            _Pragma("unroll")                                                  \
            for (int mt = 0; mt < 2; mt++) {                                   \
                uint32_t addr = (stA_) + s * ATILE + aRB + mt * 2048 +         \
                                (uint32_t)(((aC + 2 * (ks)) ^ aXor) << 4);     \
                LDSM_X4(fa[q][s][mt][0], fa[q][s][mt][1],                      \
                        fa[q][s][mt][2], fa[q][s][mt][3], addr);               \
            }                                                                  \
            _Pragma("unroll")                                                  \
            for (int np = 0; np < 2; np++) {                                   \
                uint32_t addr = (stB_) + s * BTILE + bRB + np * 2048 +         \
                                (uint32_t)(((bC + 2 * (ks)) ^ bXor) << 4);     \
                LDSM_X4(fb[q][s][np][0], fb[q][s][np][1],                      \
                        fb[q][s][np][2], fb[q][s][np][3], addr);               \
            }                                                                  \
        }                                                                      \
    } while (0)

    float tot[2][4][4];   // fp32 total of hH chunks (RN folds)
    float ah[2][4][4];    // per-chunk hH accumulator
    float al[2][4][4];    // persistent scaled-residual accumulator
    uint32_t fa[2][2][2][4];
    uint32_t fb[2][2][2][4];
#pragma unroll
    for (int mt = 0; mt < 2; mt++)
#pragma unroll
        for (int nt = 0; nt < 4; nt++)
#pragma unroll
            for (int e = 0; e < 4; e++) { tot[mt][nt][e] = 0.0f; al[mt][nt][e] = 0.0f; }

    ISSUE_STAGE(0);
    ISSUE_STAGE(1);

    for (int c = 0; c < NCHUNK; ++c) {
        if (c + 2 < NCHUNK) {
            ISSUE_STAGE(c + 2);
            CP_WAIT2();
        } else if (c == NCHUNK - 2) {
            CP_WAIT1();
        } else {
            CP_WAIT0();
        }
        __syncthreads();   // single barrier per chunk (4-stage ring)

        const uint32_t stA = sb + (c & (NSTAGE - 1)) * STAGE_B;
        const uint32_t stB = stA + BOFF;

        // zero the per-chunk hH accumulator
#pragma unroll
        for (int mt = 0; mt < 2; mt++)
#pragma unroll
            for (int nt = 0; nt < 4; nt++)
#pragma unroll
                for (int e = 0; e < 4; e++) ah[mt][nt][e] = 0.0f;

        LOAD_FRAGS(0, 0, stA, stB);   // prologue fragments for ks=0

#pragma unroll
        for (int ks = 0; ks < 4; ++ks) {
            const int q = ks & 1;
            if (ks < 3) LOAD_FRAGS((ks + 1) & 1, ks + 1, stA, stB);  // prefetch
            // p0: h*H -> ah
#pragma unroll
            for (int mt = 0; mt < 2; mt++)
#pragma unroll
                for (int np = 0; np < 2; np++) {
                    MMA16816F16(ah[mt][2 * np + 0], fa[q][0][mt], fb[q][0][np][0], fb[q][0][np][1]);
                    MMA16816F16(ah[mt][2 * np + 1], fa[q][0][mt], fb[q][0][np][2], fb[q][0][np][3]);
                }
            // p1: h*M' -> al
#pragma unroll
            for (int mt = 0; mt < 2; mt++)
#pragma unroll
                for (int np = 0; np < 2; np++) {
                    MMA16816F16(al[mt][2 * np + 0], fa[q][0][mt], fb[q][1][np][0], fb[q][1][np][1]);
                    MMA16816F16(al[mt][2 * np + 1], fa[q][0][mt], fb[q][1][np][2], fb[q][1][np][3]);
                }
            // p2: m'*H -> al
#pragma unroll
            for (int mt = 0; mt < 2; mt++)
#pragma unroll
                for (int np = 0; np < 2; np++) {
                    MMA16816F16(al[mt][2 * np + 0], fa[q][1][mt], fb[q][0][np][0], fb[q][0][np][1]);
                    MMA16816F16(al[mt][2 * np + 1], fa[q][1][mt], fb[q][0][np][2], fb[q][0][np][3]);
                }
        }
        // RN fold of the chunk's hH partial into the fp32 total
#pragma unroll
        for (int mt = 0; mt < 2; mt++)
#pragma unroll
            for (int nt = 0; nt < 4; nt++)
#pragma unroll
                for (int e = 0; e < 4; e++) tot[mt][nt][e] += ah[mt][nt][e];
    }

    // ---- epilogue: tot + al*2^-11 + bias -> sigmoid, float2 stores ----
    const float RS = 1.0f / 2048.0f;
#pragma unroll
    for (int mt = 0; mt < 2; mt++) {
        const int m0 = brow + mg * 32 + mt * 16 + (lane >> 2);
#pragma unroll
        for (int nt = 0; nt < 4; nt++) {
            const int n0 = bcol + ng * 32 + nt * 8 + 2 * (lane & 3);
            const float2 bb = *(const float2*)&bias[n0];
            float2 o0, o1;
            o0.x = sigmoid_acc(fmaf(al[mt][nt][0], RS, tot[mt][nt][0]) + bb.x);
            o0.y = sigmoid_acc(fmaf(al[mt][nt][1], RS, tot[mt][nt][1]) + bb.y);
            o1.x = sigmoid_acc(fmaf(al[mt][nt][2], RS, tot[mt][nt][2]) + bb.x);
            o1.y = sigmoid_acc(fmaf(al[mt][nt][3], RS, tot[mt][nt][3]) + bb.y);
            *(float2*)&S[(size_t)m0 * D_DIM + n0]       = o0;
            *(float2*)&S[(size_t)(m0 + 8) * D_DIM + n0] = o1;
        }
    }
}

// ============================ top-k mask =====================================
// 2 radix passes (16-bit prefix) + tie-class candidate ranking (round 11).
__global__ __launch_bounds__(256)
void topk_mask_kernel(const float* __restrict__ X, const float* __restrict__ S,
                      float* __restrict__ O) {
    const int row = blockIdx.x;
    const int t   = threadIdx.x;
    const int lane = t & 31, wrp = t >> 5;
    const size_t base = (size_t)row * D_DIM;

    const uint4 u = ((const uint4*)(S + base))[t];

    __shared__ int hist[256];
    __shared__ int sscan[256];
    __shared__ int wsum[8];
    __shared__ uint32_t sh_pref;
    __shared__ int sh_need;
    __shared__ int ccount;
    __shared__ uint32_t candv[64];
    __shared__ uint16_t candi[64];
    __shared__ uint32_t selbmp[32];

    uint32_t prefix = 0;
    int need = K_TOP;

#pragma unroll
    for (int p = 0; p < 2; p++) {
        const int shift = 24 - (p << 3);
        const uint32_t dm = (p == 0) ? 0u : 0xFF000000u;
        hist[t] = 0;
        __syncthreads();
        if ((u.x & dm) == prefix) atomicAdd(&hist[(u.x >> shift) & 255], 1);
        if ((u.y & dm) == prefix) atomicAdd(&hist[(u.y >> shift) & 255], 1);
        if ((u.z & dm) == prefix) atomicAdd(&hist[(u.z >> shift) & 255], 1);
        if ((u.w & dm) == prefix) atomicAdd(&hist[(u.w >> shift) & 255], 1);
        __syncthreads();
        int s = hist[t];
#pragma unroll
        for (int off = 1; off < 32; off <<= 1) {
            int v = __shfl_down_sync(0xffffffffu, s, off);
            if (lane + off < 32) s += v;
        }
        if (lane == 0) wsum[wrp] = s;
        __syncthreads();
        int add = 0;
#pragma unroll
        for (int w2 = 0; w2 < 8; w2++) add += (w2 > wrp) ? wsum[w2] : 0;
        const int ge = s + add;
        sscan[t] = ge;
        __syncthreads();
        const int nxt = (t < 255) ? sscan[t + 1] : 0;
        if (ge >= need && nxt < need) {
            sh_pref = prefix | ((uint32_t)t << shift);
            sh_need = need - nxt;
        }
        __syncthreads();
        prefix = sh_pref;
        need   = sh_need;
    }

    // ---- gather tie-class candidates (top16 == prefix bits) ----
    if (t == 0) ccount = 0;
    if (t < 32) selbmp[t] = 0;
    __syncthreads();
    const uint32_t p16 = prefix;
    const int idx0 = t << 2;
    {
        const uint32_t vv[4] = {u.x, u.y, u.z, u.w};
#pragma unroll
        for (int k = 0; k < 4; k++) {
            if ((vv[k] & 0xFFFF0000u) == p16) {
                int pos = atomicAdd(&ccount, 1);
                if (pos < 64) { candv[pos] = vv[k]; candi[pos] = (uint16_t)(idx0 + k); }
            }
        }
    }
    __syncthreads();
    const int cnt = ccount;

    const float4 xv = ((const float4*)(X + base))[t];
    float4 o;

    if (cnt <= 64) {
        if (t < cnt) {
            const uint32_t v = candv[t];
            const uint32_t idx = candi[t];
            int r = 0;
            for (int j = 0; j < cnt; j++) {
                const uint32_t vj = candv[j];
                r += (vj > v) || (vj == v && candi[j] < idx);
            }
            if (r < need) atomicOr(&selbmp[idx >> 5], 1u << (idx & 31));
        }
        __syncthreads();
        const uint32_t h0 = u.x & 0xFFFF0000u, h1 = u.y & 0xFFFF0000u;
        const uint32_t h2 = u.z & 0xFFFF0000u, h3 = u.w & 0xFFFF0000u;
        const bool s0 = (h0 > p16) || (h0 == p16 && ((selbmp[(idx0 + 0) >> 5] >> ((idx0 + 0) & 31)) & 1u));
        const bool s1 = (h1 > p16) || (h1 == p16 && ((selbmp[(idx0 + 1) >> 5] >> ((idx0 + 1) & 31)) & 1u));
        const bool s2 = (h2 > p16) || (h2 == p16 && ((selbmp[(idx0 + 2) >> 5] >> ((idx0 + 2) & 31)) & 1u));
        const bool s3 = (h3 > p16) || (h3 == p16 && ((selbmp[(idx0 + 3) >> 5] >> ((idx0 + 3) & 31)) & 1u));
        o.x = s0 ? xv.x : 0.0f;
        o.y = s1 ? xv.y : 0.0f;
        o.z = s2 ? xv.z : 0.0f;
        o.w = s3 ? xv.w : 0.0f;
    } else {
        // ---- fallback: finish radix passes 2,3 then rank ties (rare) ----
        __syncthreads();
#pragma unroll
        for (int p = 2; p < 4; p++) {
            const int shift = 24 - (p << 3);
            const uint32_t dm = (p == 2) ? 0xFFFF0000u : 0xFFFFFF00u;
            hist[t] = 0;
            __syncthreads();
            if ((u.x & dm) == prefix) atomicAdd(&hist[(u.x >> shift) & 255], 1);
            if ((u.y & dm) == prefix) atomicAdd(&hist[(u.y >> shift) & 255], 1);
            if ((u.z & dm) == prefix) atomicAdd(&hist[(u.z >> shift) & 255], 1);
            if ((u.w & dm) == prefix) atomicAdd(&hist[(u.w >> shift) & 255], 1);
            __syncthreads();
            int s = hist[t];
#pragma unroll
            for (int off = 1; off < 32; off <<= 1) {
                int v = __shfl_down_sync(0xffffffffu, s, off);
                if (lane + off < 32) s += v;
            }
            if (lane == 0) wsum[wrp] = s;
            __syncthreads();
            int add = 0;
#pragma unroll
            for (int w2 = 0; w2 < 8; w2++) add += (w2 > wrp) ? wsum[w2] : 0;
            const int ge = s + add;
            sscan[t] = ge;
            __syncthreads();
            const int nxt = (t < 255) ? sscan[t + 1] : 0;
            if (ge >= need && nxt < need) {
                sh_pref = prefix | ((uint32_t)t << shift);
                sh_need = need - nxt;
            }
            __syncthreads();
            prefix = sh_pref;
            need   = sh_need;
            __syncthreads();
        }
        const uint32_t T = prefix;
        const int e0 = (u.x == T), e1 = (u.y == T), e2 = (u.z == T), e3 = (u.w == T);
        const int cnt4 = e0 + e1 + e2 + e3;
        int incl = cnt4;
#pragma unroll
        for (int off = 1; off < 32; off <<= 1) {
            int v = __shfl_up_sync(0xffffffffu, incl, off);
            if (lane >= off) incl += v;
        }
        if (lane == 31) wsum[wrp] = incl;
        __syncthreads();
        if (t == 0) {
            int ssum = 0;
#pragma unroll
            for (int i = 0; i < 8; i++) { int v = wsum[i]; wsum[i] = ssum; ssum += v; }
        }
        __syncthreads();
        int rank = wsum[wrp] + (incl - cnt4);
        const bool s0 = (u.x > T) || (e0 && rank < need); rank += e0;
        const bool s1 = (u.y > T) || (e1 && rank < need); rank += e1;
        const bool s2 = (u.z > T) || (e2 && rank < need); rank += e2;
        const bool s3 = (u.w > T) || (e3 && rank < need);
        o.x = s0 ? xv.x : 0.0f;
        o.y = s1 ? xv.y : 0.0f;
        o.z = s2 ? xv.z : 0.0f;
        o.w = s3 ? xv.w : 0.0f;
    }
    ((float4*)(O + base))[t] = o;
}

// ============================ launch =========================================
extern "C" void kernel_launch(void* const* d_in, const int* in_sizes, int n_in,
                              void* d_out, int out_size) {
    const float* X = (const float*)d_in[0];  // [N, 1024]
    const float* W = (const float*)d_in[1];  // [1024, 1024]
    const float* b = (const float*)d_in[2];  // [1024]
    float* out = (float*)d_out;              // [2, N, 1024]

    const int N = in_sizes[0] / D_DIM;
    float* S = out + (size_t)N * D_DIM;

    uint16_t *wh, *wm, *xh, *xm;
    cudaGetSymbolAddress((void**)&wh, g_Wh);
    cudaGetSymbolAddress((void**)&wm, g_Wm);
    cudaGetSymbolAddress((void**)&xh, g_Xh);
    cudaGetSymbolAddress((void**)&xm, g_Xm);

    cudaFuncSetAttribute(gemm_hmma_kernel,
                         cudaFuncAttributeMaxDynamicSharedMemorySize, SMEM_GEMM);

    split2_kernel<<<D_DIM * D_DIM / 8 / 256, 256>>>(W, wh, wm);
    split2_kernel<<<(int)((size_t)N * D_DIM / 8 / 256), 256>>>(X, xh, xm);
    gemm_hmma_kernel<<<dim3(D_DIM / 128, N / 64), 256, SMEM_GEMM>>>(b, S);
    topk_mask_kernel<<<N, 256>>>(X, S, out);
}

// round 14
// speedup vs baseline: 1.9120x; 1.5580x over previous
#include <cuda_runtime.h>
#include <cuda_fp16.h>
#include <cstdint>

#define D_DIM 1024
#define K_TOP 307
#define MAX_N 65536

// ============================ PTX helpers ===================================
__device__ __forceinline__ uint32_t smem_u32(const void* p) {
    uint32_t a;
    asm("{ .reg .u64 t; cvta.to.shared.u64 t, %1; cvt.u32.u64 %0, t; }" : "=r"(a) : "l"(p));
    return a;
}
#define CPA16(saddr, gptr) \
    asm volatile("cp.async.cg.shared.global [%0], [%1], 16;" :: "r"(saddr), "l"(gptr) : "memory")
#define CP_COMMIT() asm volatile("cp.async.commit_group;" ::: "memory")
#define CP_WAIT2()  asm volatile("cp.async.wait_group 2;" ::: "memory")
#define CP_WAIT1()  asm volatile("cp.async.wait_group 1;" ::: "memory")
#define CP_WAIT0()  asm volatile("cp.async.wait_group 0;" ::: "memory")

#define LDSM_X4(r0, r1, r2, r3, addr) \
    asm volatile("ldmatrix.sync.aligned.m8n8.x4.shared.b16 {%0,%1,%2,%3}, [%4];" \
        : "=r"(r0), "=r"(r1), "=r"(r2), "=r"(r3) : "r"(addr))

#define MMA16816F16(d, a, b0, b1) \
    asm volatile("mma.sync.aligned.m16n8k16.row.col.f32.f16.f16.f32 " \
        "{%0,%1,%2,%3}, {%4,%5,%6,%7}, {%8,%9}, {%0,%1,%2,%3};" \
        : "+f"((d)[0]), "+f"((d)[1]), "+f"((d)[2]), "+f"((d)[3]) \
        : "r"((a)[0]), "r"((a)[1]), "r"((a)[2]), "r"((a)[3]), "r"(b0), "r"(b1))

// ============================ numeric helpers ================================
__device__ __forceinline__ float sigmoid_acc(float z) {
    float x = -z;
    x = fminf(fmaxf(x, -87.0f), 87.0f);
    float t = x * 1.4426950408889634f;
    float n = rintf(t);
    float r = fmaf(n, -0.693145751953125f, x);
    r = fmaf(n, -1.42860676533018687e-06f, r);
    float p = 1.9875691500e-4f;
    p = fmaf(p, r, 1.3981999507e-3f);
    p = fmaf(p, r, 8.3333331174e-3f);
    p = fmaf(p, r, 4.1665795894e-2f);
    p = fmaf(p, r, 1.6666665459e-1f);
    p = fmaf(p, r, 5.0000001201e-1f);
    float y = fmaf(r * r, p, r) + 1.0f;
    int   i  = (int)n;
    float sc = __int_as_float((i + 127) << 23);
    return 1.0f / (1.0f + y * sc);
}

// ============================ pre-split storage ==============================
__device__ __align__(16) uint16_t g_Wh[D_DIM * D_DIM];
__device__ __align__(16) uint16_t g_Xh[(size_t)MAX_N * D_DIM];

__global__ __launch_bounds__(256)
void split1_kernel(const float* __restrict__ src, uint16_t* __restrict__ oh) {
    size_t gid = (size_t)blockIdx.x * 256 + threadIdx.x;  // one 8-float group
    float4 a = ((const float4*)src)[2 * gid];
    float4 c = ((const float4*)src)[2 * gid + 1];
    float v[8] = {a.x, a.y, a.z, a.w, c.x, c.y, c.z, c.w};
    uint16_t h[8];
#pragma unroll
    for (int i = 0; i < 8; i++) h[i] = __half_as_ushort(__float2half_rn(v[i]));
    uint4 H = {(uint32_t)h[0] | ((uint32_t)h[1] << 16), (uint32_t)h[2] | ((uint32_t)h[3] << 16),
               (uint32_t)h[4] | ((uint32_t)h[5] << 16), (uint32_t)h[6] | ((uint32_t)h[7] << 16)};
    ((uint4*)oh)[gid] = H;
}

// ============================ GEMM (single-product HMMA) =====================
// CTA tile 64(M) x 128(N), K chunks of 64, 4-stage cp.async ring, 2 CTAs/SM.
// Single product hH -> per-chunk ah, RN-folded into fp32 tot (bias control).
#define ATILE   8192                    // 64 x 64 fp16
#define BTILE   16384                   // 128 x 64 fp16
#define BOFF    ATILE
#define STAGE_B (ATILE + BTILE)         // 24576
#define NSTAGE  4
#define SMEM_GEMM (NSTAGE * STAGE_B)    // 98304
#define NCHUNK  (D_DIM / 64)            // 16

__global__ __launch_bounds__(256, 2)
void gemm_hmma_kernel(const float* __restrict__ bias, float* __restrict__ S) {
    extern __shared__ char smem[];
    const uint32_t sb = smem_u32(smem);
    const int tid  = threadIdx.x;
    const int lane = tid & 31;
    const int wid  = tid >> 5;
    const int mg   = wid >> 2;          // 0..1 : rows mg*32..+32
    const int ng   = wid & 3;           // 0..3 : cols ng*32..+32
    const int brow = blockIdx.y << 6;   // 64-row tile
    const int bcol = blockIdx.x << 7;   // 128-col tile

#define ISSUE_STAGE(c)                                                        \
    do {                                                                      \
        const int k0_ = (c) * 64;                                             \
        const uint32_t st_ = sb + ((c) & (NSTAGE - 1)) * STAGE_B;             \
        _Pragma("unroll")                                                     \
        for (int j = 0; j < 2; j++) {                                         \
            int g = tid + j * 256;                                            \
            int row = g >> 3, cc = g & 7;                                     \
            uint32_t sw = (uint32_t)(row * 128 + ((cc ^ (row & 7)) << 4));    \
            size_t ga = (size_t)(brow + row) * D_DIM + k0_ + cc * 8;          \
            CPA16(st_ + sw, g_Xh + ga);                                       \
        }                                                                     \
        _Pragma("unroll")                                                     \
        for (int j = 0; j < 4; j++) {                                         \
            int g = tid + j * 256;                                            \
            int row = g >> 3, cc = g & 7;                                     \
            uint32_t sw = (uint32_t)(row * 128 + ((cc ^ (row & 7)) << 4));    \
            size_t gb = (size_t)(bcol + row) * D_DIM + k0_ + cc * 8;          \
            CPA16(st_ + BOFF + sw, g_Wh + gb);                                \
        }                                                                     \
        CP_COMMIT();                                                          \
    } while (0)

    // ---- ldmatrix lane addressing (validated rounds 8-13) ----
    const int aRow = mg * 32 + (((lane >> 3) & 1) << 3) + (lane & 7);   // <64
    const int aC   = (lane >> 4);
    const uint32_t aRB = (uint32_t)(aRow * 128);
    const int aXor = aRow & 7;
    const int bRow = ng * 32 + (((lane >> 4) & 1) << 3) + (lane & 7);   // <128
    const int bC   = (lane >> 3) & 1;
    const uint32_t bRB = (uint32_t)(bRow * 128);
    const int bXor = bRow & 7;

#define LOAD_FRAGS(q, ks, stA_, stB_)                                          \
    do {                                                                       \
        _Pragma("unroll")                                                      \
        for (int mt = 0; mt < 2; mt++) {                                       \
            uint32_t addr = (stA_) + aRB + mt * 2048 +                         \
                            (uint32_t)(((aC + 2 * (ks)) ^ aXor) << 4);         \
            LDSM_X4(fa[q][mt][0], fa[q][mt][1], fa[q][mt][2], fa[q][mt][3], addr); \
        }                                                                      \
        _Pragma("unroll")                                                      \
        for (int np = 0; np < 2; np++) {                                       \
            uint32_t addr = (stB_) + bRB + np * 2048 +                         \
                            (uint32_t)(((bC + 2 * (ks)) ^ bXor) << 4);         \
            LDSM_X4(fb[q][np][0], fb[q][np][1], fb[q][np][2], fb[q][np][3], addr); \
        }                                                                      \
    } while (0)

    float tot[2][4][4];
    float ah[2][4][4];
    uint32_t fa[2][2][4];
    uint32_t fb[2][2][4];
#pragma unroll
    for (int mt = 0; mt < 2; mt++)
#pragma unroll
        for (int nt = 0; nt < 4; nt++)
#pragma unroll
            for (int e = 0; e < 4; e++) tot[mt][nt][e] = 0.0f;

    ISSUE_STAGE(0);
    ISSUE_STAGE(1);

    for (int c = 0; c < NCHUNK; ++c) {
        if (c + 2 < NCHUNK) {
            ISSUE_STAGE(c + 2);
            CP_WAIT2();
        } else if (c == NCHUNK - 2) {
            CP_WAIT1();
        } else {
            CP_WAIT0();
        }
        __syncthreads();

        const uint32_t stA = sb + (c & (NSTAGE - 1)) * STAGE_B;
        const uint32_t stB = stA + BOFF;

#pragma unroll
        for (int mt = 0; mt < 2; mt++)
#pragma unroll
            for (int nt = 0; nt < 4; nt++)
#pragma unroll
                for (int e = 0; e < 4; e++) ah[mt][nt][e] = 0.0f;

        LOAD_FRAGS(0, 0, stA, stB);

#pragma unroll
        for (int ks = 0; ks < 4; ++ks) {
            const int q = ks & 1;
            if (ks < 3) LOAD_FRAGS((ks + 1) & 1, ks + 1, stA, stB);
#pragma unroll
            for (int mt = 0; mt < 2; mt++)
#pragma unroll
                for (int np = 0; np < 2; np++) {
                    MMA16816F16(ah[mt][2 * np + 0], fa[q][mt], fb[q][np][0], fb[q][np][1]);
                    MMA16816F16(ah[mt][2 * np + 1], fa[q][mt], fb[q][np][2], fb[q][np][3]);
                }
        }
#pragma unroll
        for (int mt = 0; mt < 2; mt++)
#pragma unroll
            for (int nt = 0; nt < 4; nt++)
#pragma unroll
                for (int e = 0; e < 4; e++) tot[mt][nt][e] += ah[mt][nt][e];
    }

    // ---- epilogue: tot + bias -> sigmoid, float2 stores ----
#pragma unroll
    for (int mt = 0; mt < 2; mt++) {
        const int m0 = brow + mg * 32 + mt * 16 + (lane >> 2);
#pragma unroll
        for (int nt = 0; nt < 4; nt++) {
            const int n0 = bcol + ng * 32 + nt * 8 + 2 * (lane & 3);
            const float2 bb = *(const float2*)&bias[n0];
            float2 o0, o1;
            o0.x = sigmoid_acc(tot[mt][nt][0] + bb.x);
            o0.y = sigmoid_acc(tot[mt][nt][1] + bb.y);
            o1.x = sigmoid_acc(tot[mt][nt][2] + bb.x);
            o1.y = sigmoid_acc(tot[mt][nt][3] + bb.y);
            *(float2*)&S[(size_t)m0 * D_DIM + n0]       = o0;
            *(float2*)&S[(size_t)(m0 + 8) * D_DIM + n0] = o1;
        }
    }
}

// ============================ top-k with exact boundary rescue ===============
// T = exact K-th largest APPROX score (radix). s > T+M -> surely in;
// s < T-M -> surely out; window candidates get exact fp32 rescoring (X.W row)
// and are ranked by (exact score desc, index asc).
#define MARGIN 2.0e-3f
#define CMAX   64

__global__ __launch_bounds__(256)
void topk_mask_kernel(const float* __restrict__ X, const float* __restrict__ S,
                      const float* __restrict__ W, const float* __restrict__ bias,
                      float* __restrict__ O) {
    const int row = blockIdx.x;
    const int t   = threadIdx.x;
    const int lane = t & 31, wrp = t >> 5;
    const size_t base = (size_t)row * D_DIM;

    const uint4 u = ((const uint4*)(S + base))[t];
    const float4 xv = ((const float4*)(X + base))[t];

    __shared__ int hist[256];
    __shared__ int sscan[256];
    __shared__ int wsum[8];
    __shared__ uint32_t sh_pref;
    __shared__ int sh_need;
    __shared__ int ccount;
    __shared__ uint32_t candv[CMAX];
    __shared__ uint32_t sh_T;
    __shared__ float xs[D_DIM];
    __shared__ int wcount;
    __shared__ int sh_csure;
    __shared__ uint16_t wci[CMAX];
    __shared__ float wcf[CMAX];
    __shared__ uint32_t selbmp[32];

    *(float4*)&xs[4 * t] = xv;          // stage X row for exact dots
    if (t < 32) selbmp[t] = 0;
    if (t == 0) { ccount = 0; wcount = 0; }

    uint32_t prefix = 0;
    int need = K_TOP;

#pragma unroll
    for (int p = 0; p < 2; p++) {
        const int shift = 24 - (p << 3);
        const uint32_t dm = (p == 0) ? 0u : 0xFF000000u;
        hist[t] = 0;
        __syncthreads();
        if ((u.x & dm) == prefix) atomicAdd(&hist[(u.x >> shift) & 255], 1);
        if ((u.y & dm) == prefix) atomicAdd(&hist[(u.y >> shift) & 255], 1);
        if ((u.z & dm) == prefix) atomicAdd(&hist[(u.z >> shift) & 255], 1);
        if ((u.w & dm) == prefix) atomicAdd(&hist[(u.w >> shift) & 255], 1);
        __syncthreads();
        int s = hist[t];
#pragma unroll
        for (int off = 1; off < 32; off <<= 1) {
            int v = __shfl_down_sync(0xffffffffu, s, off);
            if (lane + off < 32) s += v;
        }
        if (lane == 0) wsum[wrp] = s;
        __syncthreads();
        int add = 0;
#pragma unroll
        for (int w2 = 0; w2 < 8; w2++) add += (w2 > wrp) ? wsum[w2] : 0;
        const int ge = s + add;
        sscan[t] = ge;
        __syncthreads();
        const int nxt = (t < 255) ? sscan[t + 1] : 0;
        if (ge >= need && nxt < need) {
            sh_pref = prefix | ((uint32_t)t << shift);
            sh_need = need - nxt;
        }
        __syncthreads();
        prefix = sh_pref;
        need   = sh_need;
    }

    // ---- exact T (K-th largest approx score) ----
    const uint32_t p16 = prefix;
    {
        const uint32_t vv[4] = {u.x, u.y, u.z, u.w};
#pragma unroll
        for (int k = 0; k < 4; k++) {
            if ((vv[k] & 0xFFFF0000u) == p16) {
                int pos = atomicAdd(&ccount, 1);
                if (pos < CMAX) candv[pos] = vv[k];
            }
        }
    }
    __syncthreads();
    if (ccount <= CMAX) {
        if (t < ccount) {
            const uint32_t v = candv[t];
            int rs = 0, eq = 0;
            for (int j = 0; j < ccount; j++) { rs += candv[j] > v; eq += candv[j] == v; }
            if (rs < need && rs + eq >= need) sh_T = v;
        }
        __syncthreads();
    } else {
        // fallback: finish radix passes 2,3 -> exact K-th value (rare)
#pragma unroll
        for (int p = 2; p < 4; p++) {
            const int shift = 24 - (p << 3);
            const uint32_t dm = (p == 2) ? 0xFFFF0000u : 0xFFFFFF00u;
            hist[t] = 0;
            __syncthreads();
            if ((u.x & dm) == prefix) atomicAdd(&hist[(u.x >> shift) & 255], 1);
            if ((u.y & dm) == prefix) atomicAdd(&hist[(u.y >> shift) & 255], 1);
            if ((u.z & dm) == prefix) atomicAdd(&hist[(u.z >> shift) & 255], 1);
            if ((u.w & dm) == prefix) atomicAdd(&hist[(u.w >> shift) & 255], 1);
            __syncthreads();
            int s = hist[t];
#pragma unroll
            for (int off = 1; off < 32; off <<= 1) {
                int v = __shfl_down_sync(0xffffffffu, s, off);
                if (lane + off < 32) s += v;
            }
            if (lane == 0) wsum[wrp] = s;
            __syncthreads();
            int add = 0;
#pragma unroll
            for (int w2 = 0; w2 < 8; w2++) add += (w2 > wrp) ? wsum[w2] : 0;
            const int ge = s + add;
            sscan[t] = ge;
            __syncthreads();
            const int nxt = (t < 255) ? sscan[t + 1] : 0;
            if (ge >= need && nxt < need) {
                sh_pref = prefix | ((uint32_t)t << shift);
                sh_need = need - nxt;
            }
            __syncthreads();
            prefix = sh_pref;
            need   = sh_need;
            __syncthreads();
        }
        if (t == 0) sh_T = prefix;
        __syncthreads();
    }

    const float Tf = __uint_as_float(sh_T);
    const float hi = Tf + MARGIN;
    const float lo = Tf - MARGIN;
    const float sf[4] = {__uint_as_float(u.x), __uint_as_float(u.y),
                         __uint_as_float(u.z), __uint_as_float(u.w)};

    // ---- count sure-ins ----
    {
        int cs = (sf[0] > hi) + (sf[1] > hi) + (sf[2] > hi) + (sf[3] > hi);
#pragma unroll
        for (int off = 16; off; off >>= 1) cs += __shfl_down_sync(0xffffffffu, cs, off);
        if (lane == 0) wsum[wrp] = cs;
        __syncthreads();
        if (t == 0) {
            int tot = 0;
#pragma unroll
            for (int i = 0; i < 8; i++) tot += wsum[i];
            sh_csure = tot;
        }
    }

    // ---- gather window candidates ----
    const int idx0 = t << 2;
#pragma unroll
    for (int k = 0; k < 4; k++) {
        if (sf[k] >= lo && sf[k] <= hi) {
            int pos = atomicAdd(&wcount, 1);
            if (pos < CMAX) wci[pos] = (uint16_t)(idx0 + k);
        }
    }
    __syncthreads();
    const int need2 = K_TOP - sh_csure;
    const int wcnt  = (wcount <= CMAX) ? wcount : CMAX;
    const bool overflow = wcount > CMAX;

    // ---- exact fp32 rescoring of candidates: one warp per candidate ----
    if (!overflow) {
        for (int c = wrp; c < wcnt; c += 8) {
            const int e = wci[c];
            const float* wr = W + (size_t)e * D_DIM;
            float acc = 0.0f;
#pragma unroll 8
            for (int k = lane; k < D_DIM; k += 32) acc = fmaf(xs[k], wr[k], acc);
#pragma unroll
            for (int off = 16; off; off >>= 1) acc += __shfl_down_sync(0xffffffffu, acc, off);
            if (lane == 0) wcf[c] = sigmoid_acc(acc + bias[e]);
        }
        __syncthreads();
        // rank candidates: (exact score desc, index asc); select rank < need2
        if (t < wcnt) {
            const float f = wcf[t];
            const int   id = wci[t];
            int r = 0;
            for (int j = 0; j < wcnt; j++) {
                const float fj = wcf[j];
                r += (fj > f) || (fj == f && wci[j] < id);
            }
            if (r < need2) atomicOr(&selbmp[id >> 5], 1u << (id & 31));
        }
        __syncthreads();
    }

    // ---- write masked output ----
    float4 o;
    if (!overflow) {
        const bool s0 = (sf[0] > hi) || (sf[0] >= lo && ((selbmp[(idx0 + 0) >> 5] >> ((idx0 + 0) & 31)) & 1u));
        const bool s1 = (sf[1] > hi) || (sf[1] >= lo && ((selbmp[(idx0 + 1) >> 5] >> ((idx0 + 1) & 31)) & 1u));
        const bool s2 = (sf[2] > hi) || (sf[2] >= lo && ((selbmp[(idx0 + 2) >> 5] >> ((idx0 + 2) & 31)) & 1u));
        const bool s3 = (sf[3] > hi) || (sf[3] >= lo && ((selbmp[(idx0 + 3) >> 5] >> ((idx0 + 3) & 31)) & 1u));
        o.x = s0 ? xv.x : 0.0f;
        o.y = s1 ? xv.y : 0.0f;
        o.z = s2 ? xv.z : 0.0f;
        o.w = s3 ? xv.w : 0.0f;
    } else {
        // deterministic degraded path (never expected)
        o.x = (sf[0] >= Tf) ? xv.x : 0.0f;
        o.y = (sf[1] >= Tf) ? xv.y : 0.0f;
        o.z = (sf[2] >= Tf) ? xv.z : 0.0f;
        o.w = (sf[3] >= Tf) ? xv.w : 0.0f;
    }
    ((float4*)(O + base))[t] = o;
}

// ============================ launch =========================================
extern "C" void kernel_launch(void* const* d_in, const int* in_sizes, int n_in,
                              void* d_out, int out_size) {
    const float* X = (const float*)d_in[0];  // [N, 1024]
    const float* W = (const float*)d_in[1];  // [1024, 1024]
    const float* b = (const float*)d_in[2];  // [1024]
    float* out = (float*)d_out;              // [2, N, 1024]

    const int N = in_sizes[0] / D_DIM;
    float* S = out + (size_t)N * D_DIM;

    uint16_t *wh, *xh;
    cudaGetSymbolAddress((void**)&wh, g_Wh);
    cudaGetSymbolAddress((void**)&xh, g_Xh);

    cudaFuncSetAttribute(gemm_hmma_kernel,
                         cudaFuncAttributeMaxDynamicSharedMemorySize, SMEM_GEMM);

    split1_kernel<<<D_DIM * D_DIM / 8 / 256, 256>>>(W, wh);
    split1_kernel<<<(int)((size_t)N * D_DIM / 8 / 256), 256>>>(X, xh);
    gemm_hmma_kernel<<<dim3(D_DIM / 128, N / 64), 256, SMEM_GEMM>>>(b, S);
    topk_mask_kernel<<<N, 256>>>(X, S, W, b, out);
}